// round 12
// baseline (speedup 1.0000x reference)
#include <cuda_runtime.h>
#include <cuda_bf16.h>

// BPMLL loss — single graph node, packed-atomic tail, per-row leaders.
//   256 blocks x 256 threads; 128 threads/row (2 rows/block), 4 elems/thread.
//   Warp reduce: two interleaved shfl_xor butterflies (measured faster than
//   integer redux+cvt on this part). Counts via ballot+popc.
//   Tail: TWO leaders per block (tid 0 -> row 0, tid 128 -> row 1); each
//   combines only its own row (12 LDS, one fdividef) and fires its own packed
//   atom.add.u64 {count:bits>=52, fixed-sum(2^44):bits<52}. 512 single-address
//   REDs pipeline at L2; the leader whose returned count == 511 holds the
//   grand total in old+add, writes out[0], resets g_pack for graph replay.
//
// Math per element (2 MUFU + 4 FMA):
//   exp(-sigmoid(c)) = e^{-1} * exp(sigmoid(-c)) -> h(x)=exp(sigmoid(x)),
//   x = y ? -c : c. sigmoid = EX2+RCP; exp(s), s in (0,1), degree-4 poly.

#define ROWS 512
#define COLS 512
#define NBLK 256
#define TPB  256
#define NARRIVE (2 * NBLK)   // two leader atomics per block

#define D0 1.00002694f
#define D1 0.99871530f
#define D2 0.50996560f
#define D3 0.13998530f
#define D4 0.06956140f
#define E_INV_OVER_ROWS (0.36787944117144233f / 512.0f)

#define CNT_ONE   (1ULL << 52)
#define SUM_MASK  ((1ULL << 52) - 1ULL)
#define FIX_SCALE 0x1p44f
#define FIX_INV   0x1p-44f

__device__ unsigned long long g_pack = 0ULL;

__device__ __forceinline__ void elem(float c, int y, float& pos, float& neg) {
    float x = __int_as_float(__float_as_int(c) ^ (y << 31));  // y ? -c : c
    float t = __expf(-x);                                     // MUFU.EX2
    float s;
    asm("rcp.approx.f32 %0, %1;" : "=f"(s) : "f"(1.0f + t));  // MUFU.RCP
    float h = fmaf(s, D4, D3);
    h = fmaf(h, s, D2);
    h = fmaf(h, s, D1);
    h = fmaf(h, s, D0);
    if (y) pos += h; else neg += h;
}

__global__ __launch_bounds__(TPB) void bpmll_kernel(const float* __restrict__ c,
                                                    const int*   __restrict__ y,
                                                    float* __restrict__ out) {
    const int tid    = threadIdx.x;
    const int lane   = tid & 31;
    const int warp   = tid >> 5;          // 0..7
    const int tid128 = tid & 127;
    const int row    = blockIdx.x * 2 + (tid >> 7);

    const float4 cv = reinterpret_cast<const float4*>(c)[(size_t)row * (COLS / 4) + tid128];
    const int4   yv = reinterpret_cast<const int4*>(y)[(size_t)row * (COLS / 4) + tid128];

    float pos = 0.0f, neg = 0.0f;
    elem(cv.x, yv.x, pos, neg);
    elem(cv.y, yv.y, pos, neg);
    elem(cv.z, yv.z, pos, neg);
    elem(cv.w, yv.w, pos, neg);

    // Label count: 4 ballots + popc.
    int ys = __popc(__ballot_sync(0xFFFFFFFFu, yv.x))
           + __popc(__ballot_sync(0xFFFFFFFFu, yv.y))
           + __popc(__ballot_sync(0xFFFFFFFFu, yv.z))
           + __popc(__ballot_sync(0xFFFFFFFFu, yv.w));

    // Two interleaved butterfly chains — latency overlaps.
    #pragma unroll
    for (int o = 16; o > 0; o >>= 1) {
        pos += __shfl_xor_sync(0xFFFFFFFFu, pos, o);
        neg += __shfl_xor_sync(0xFFFFFFFFu, neg, o);
    }

    __shared__ float sp[8];
    __shared__ float sn[8];
    __shared__ int   si[8];
    if (lane == 0) { sp[warp] = pos; sn[warp] = neg; si[warp] = ys; }
    __syncthreads();

    if (tid128 == 0) {  // tid 0 (row 0, warps 0-3) and tid 128 (row 1, warps 4-7)
        const int b = (tid >> 7) * 4;
        float P = (sp[b] + sp[b + 1]) + (sp[b + 2] + sp[b + 3]);
        float N = (sn[b] + sn[b + 1]) + (sn[b + 2] + sn[b + 3]);
        int   Y = (si[b] + si[b + 1]) + (si[b + 2] + si[b + 3]);
        float part = __fdividef(P * N * E_INV_OVER_ROWS,
                                (float)Y * (float)(COLS - Y));

        // Packed count+sum atomic: one L2 round trip per row leader.
        unsigned long long add = CNT_ONE + __float2ull_rn(part * FIX_SCALE);
        unsigned long long old;
        asm volatile("atom.global.add.u64 %0, [%1], %2;"
                     : "=l"(old) : "l"(&g_pack), "l"(add) : "memory");

        if ((old >> 52) == (unsigned long long)(NARRIVE - 1)) {
            unsigned long long total_fix = (old + add) & SUM_MASK;
            out[0] = (float)((double)total_fix) * FIX_INV;
            asm volatile("st.global.cg.u64 [%0], %1;"
                         :: "l"(&g_pack), "l"(0ULL) : "memory");
        }
    }
}

extern "C" void kernel_launch(void* const* d_in, const int* in_sizes, int n_in,
                              void* d_out, int out_size) {
    const float* c = (const float*)d_in[0];
    const int*   y = (const int*)d_in[1];
    float*       out = (float*)d_out;
    bpmll_kernel<<<NBLK, TPB>>>(c, y, out);
}

// round 13
// speedup vs baseline: 1.0385x; 1.0385x over previous
#include <cuda_runtime.h>
#include <cuda_bf16.h>

// BPMLL loss — single graph node, packed-atomic tail, 1-MUFU element math.
//   Identity: sigmoid(x) = 1/2 + tanh(x/2)/2, so
//     exp(sigmoid(x)) = e^{1/2} * exp(tanh(x/2)/2)
//   and with pos needing exp(-sigmoid(c)) = e^{-1} e^{1/2} exp(tanh(-c/2)/2),
//   ALL constant factors cancel in pos*neg*e^{-1}. Per element:
//     t = tanh.approx(0.5 * (y ? -c : c))   [1 MUFU]
//     h = poly4(t) ~= exp(t/2), t in (-1,1) [4 FMA, err ~4e-5]
//   256 blocks x 256 threads; 128 threads/row (2 rows/block), 4 elems/thread.
//   Row reduce: ballot+popc counts + two interleaved shfl_xor butterflies.
//   Tail: ONE atom.add.u64 per block packing {count >=bit52, fixed sum(2^44)};
//   the block seeing count==NBLK-1 holds the total in old+add, writes out,
//   resets g_pack for graph replay.

#define ROWS 512
#define COLS 512
#define NBLK 256
#define TPB  256

// exp(t/2) on t in [-1,1], Chebyshev-economized degree 4 (coeffs in t-basis)
#define P0 1.0f
#define P1 0.49991862f
#define P2 0.125f
#define P3 0.021158854f
#define P4 0.0026041667f

#define INV_ROWS (1.0f / 512.0f)

#define CNT_ONE   (1ULL << 52)
#define SUM_MASK  ((1ULL << 52) - 1ULL)
#define FIX_SCALE 0x1p44f
#define FIX_INV   0x1p-44f

__device__ unsigned long long g_pack = 0ULL;

__device__ __forceinline__ void elem(float c, int y, float& pos, float& neg) {
    // x = 0.5 * (y ? -c : c): fold sign via xor, then one FMUL.
    float x = __int_as_float(__float_as_int(c) ^ (y << 31)) * 0.5f;
    float t;
    asm("tanh.approx.f32 %0, %1;" : "=f"(t) : "f"(x));   // 1 MUFU
    float h = fmaf(t, P4, P3);
    h = fmaf(h, t, P2);
    h = fmaf(h, t, P1);
    h = fmaf(h, t, P0);
    if (y) pos += h; else neg += h;
}

__global__ __launch_bounds__(TPB) void bpmll_kernel(const float* __restrict__ c,
                                                    const int*   __restrict__ y,
                                                    float* __restrict__ out) {
    const int tid    = threadIdx.x;
    const int lane   = tid & 31;
    const int warp   = tid >> 5;          // 0..7
    const int tid128 = tid & 127;
    const int row    = blockIdx.x * 2 + (tid >> 7);

    const float4 cv = reinterpret_cast<const float4*>(c)[(size_t)row * (COLS / 4) + tid128];
    const int4   yv = reinterpret_cast<const int4*>(y)[(size_t)row * (COLS / 4) + tid128];

    float pos = 0.0f, neg = 0.0f;
    elem(cv.x, yv.x, pos, neg);
    elem(cv.y, yv.y, pos, neg);
    elem(cv.z, yv.z, pos, neg);
    elem(cv.w, yv.w, pos, neg);

    // Label count: 4 ballots + popc.
    int ys = __popc(__ballot_sync(0xFFFFFFFFu, yv.x))
           + __popc(__ballot_sync(0xFFFFFFFFu, yv.y))
           + __popc(__ballot_sync(0xFFFFFFFFu, yv.z))
           + __popc(__ballot_sync(0xFFFFFFFFu, yv.w));

    // Two interleaved butterfly chains — latency overlaps.
    #pragma unroll
    for (int o = 16; o > 0; o >>= 1) {
        pos += __shfl_xor_sync(0xFFFFFFFFu, pos, o);
        neg += __shfl_xor_sync(0xFFFFFFFFu, neg, o);
    }

    __shared__ float sp[8];
    __shared__ float sn[8];
    __shared__ int   si[8];
    if (lane == 0) { sp[warp] = pos; sn[warp] = neg; si[warp] = ys; }
    __syncthreads();

    if (tid == 0) {
        float P0s = (sp[0] + sp[1]) + (sp[2] + sp[3]);
        float N0s = (sn[0] + sn[1]) + (sn[2] + sn[3]);
        int   Y0  = (si[0] + si[1]) + (si[2] + si[3]);
        float P1s = (sp[4] + sp[5]) + (sp[6] + sp[7]);
        float N1s = (sn[4] + sn[5]) + (sn[6] + sn[7]);
        int   Y1  = (si[4] + si[5]) + (si[6] + si[7]);
        // All e^{+-1/2} and the e^{-1} bias cancel exactly: just P*N/(512*Y*Ybar).
        float part = __fdividef(P0s * N0s * INV_ROWS,
                                (float)Y0 * (float)(COLS - Y0))
                   + __fdividef(P1s * N1s * INV_ROWS,
                                (float)Y1 * (float)(COLS - Y1));

        unsigned long long add = CNT_ONE + __float2ull_rn(part * FIX_SCALE);
        unsigned long long old;
        asm volatile("atom.global.add.u64 %0, [%1], %2;"
                     : "=l"(old) : "l"(&g_pack), "l"(add) : "memory");

        if ((old >> 52) == (unsigned long long)(NBLK - 1)) {
            unsigned long long total_fix = (old + add) & SUM_MASK;
            out[0] = (float)((double)total_fix) * FIX_INV;
            asm volatile("st.global.cg.u64 [%0], %1;"
                         :: "l"(&g_pack), "l"(0ULL) : "memory");
        }
    }
}

extern "C" void kernel_launch(void* const* d_in, const int* in_sizes, int n_in,
                              void* d_out, int out_size) {
    const float* c = (const float*)d_in[0];
    const int*   y = (const int*)d_in[1];
    float*       out = (float*)d_out;
    bpmll_kernel<<<NBLK, TPB>>>(c, y, out);
}